// round 1
// baseline (speedup 1.0000x reference)
#include <cuda_runtime.h>
#include <math.h>

#define N 8192
#define D 10
#define TILE 256
#define NT (N / TILE)              // 32 tiles
#define NPAIRS (NT * (NT + 1) / 2) // 528 tile pairs (jt <= it)
#define PAD 11                     // smem row stride, coprime with 32 banks

// ---- scratch (static device globals: no allocation) ----
__device__ float  g_b2[D * D];      // beta * log2(e)
__device__ float  g_ab[D * D];      // alpha * beta
__device__ float  g_alpha[D * D];   // alpha
__device__ float  g_mus[D];         // softplus(mu)
__device__ float  g_partial[NT * N];// [jt][i] partial intensity sums
__device__ double g_block[NT];      // per-block reduction results

__device__ __forceinline__ float ex2(float x) {
    float y;
    asm("ex2.approx.ftz.f32 %0, %1;" : "=f"(y) : "f"(x));
    return y;
}

__device__ __forceinline__ float softplus_f(float x) {
    // stable: max(x,0) + log1p(exp(-|x|))
    return fmaxf(x, 0.f) + log1pf(expf(-fabsf(x)));
}

// T may arrive as int32(100) or float32(100.0); decode robustly.
__device__ __forceinline__ float decodeT(const int* Tp) {
    int b = *Tp;
    if (b >= 0 && b < (1 << 23)) return (float)b; // small int -> integer T
    return __int_as_float(b);                     // otherwise float bits
}

// ---- kernel 0: softplus tables ----
__global__ void k_tables(const float* __restrict__ mu,
                         const float* __restrict__ la,
                         const float* __restrict__ lb) {
    int tid = threadIdx.x;
    if (tid < D * D) {
        float a = softplus_f(la[tid]);
        float b = softplus_f(lb[tid]);
        g_alpha[tid] = a;
        g_b2[tid]    = b * 1.4426950408889634f; // log2(e)
        g_ab[tid]    = a * b;
    }
    if (tid < D) g_mus[tid] = softplus_f(mu[tid]);
}

// ---- kernel 1: tiled pairwise interactions (factorized, zero MUFU inner loop) ----
__global__ void __launch_bounds__(TILE)
k_tiles(const float* __restrict__ t, const int* __restrict__ et) {
    int bid = blockIdx.x;
    // decode lower-triangular tile pair: bid = it*(it+1)/2 + jt, jt <= it
    int it = (int)((sqrtf(8.f * (float)bid + 1.f) - 1.f) * 0.5f);
    while ((it + 1) * (it + 2) / 2 <= bid) ++it;
    while (it * (it + 1) / 2 > bid) --it;
    int jt = bid - it * (it + 1) / 2;

    __shared__ float ts[TILE];
    __shared__ int   es[TILE];
    __shared__ float b2s[D * D];
    __shared__ float abt[D * D];
    __shared__ float F[TILE * PAD];
    __shared__ float G[TILE * PAD];

    int tid = threadIdx.x;
    if (tid < D * D) { b2s[tid] = g_b2[tid]; abt[tid] = g_ab[tid]; }

    int j0 = jt * TILE;
    ts[tid] = t[j0 + tid];
    es[tid] = et[j0 + tid];
    __syncthreads();

    float tref = ts[TILE - 1]; // max time of j-tile (sorted input)

    // Stage G for own j = tid: G[j][k] = 2^(b2[k][ej] * (tj - tref))  (<= 1)
    {
        float dtj = ts[tid] - tref;
        int   ej  = es[tid];
#pragma unroll
        for (int k = 0; k < D; k++)
            G[tid * PAD + k] = ex2(b2s[k * D + ej] * dtj);
    }

    // Stage F for own i: F[i][m] = ab[ei][m] * 2^(-b2[ei][m] * (ti - tref))
    int   i  = it * TILE + tid;
    float ti = t[i];
    int   ei = et[i];
    {
        float dti = ti - tref;
#pragma unroll
        for (int m = 0; m < D; m++)
            F[tid * PAD + m] = abt[ei * D + m] * ex2(-b2s[ei * D + m] * dti);
    }
    __syncthreads();

    float acc = 0.f;
    const float* Frow = &F[tid * PAD];
    if (it != jt) {
#pragma unroll 8
        for (int j = 0; j < TILE; j++) {
            int ej = es[j];
            acc = fmaf(Frow[ej], G[j * PAD + ei], acc);
        }
    } else {
        for (int j = 0; j < tid; j++) { // strict lower triangle
            int ej = es[j];
            acc = fmaf(Frow[ej], G[j * PAD + ei], acc);
        }
    }
    g_partial[jt * N + i] = acc; // coalesced
}

// ---- kernel 2: per-event intensity, log, integral term; per-block double reduce ----
__global__ void __launch_bounds__(TILE)
k_final(const float* __restrict__ t, const int* __restrict__ et,
        const int* __restrict__ Tp) {
    int tid = threadIdx.x;
    int it  = blockIdx.x;
    int i   = it * TILE + tid;

    __shared__ float alphas[D * D], b2s[D * D], mus[D];
    if (tid < D * D) { alphas[tid] = g_alpha[tid]; b2s[tid] = g_b2[tid]; }
    if (tid < D) mus[tid] = g_mus[tid];
    __syncthreads();

    float Tf = decodeT(Tp);
    float ti = t[i];
    int   ei = et[i];

    float s = mus[ei];
    for (int jt = 0; jt <= it; jt++)
        s += g_partial[jt * N + i]; // coalesced, fixed order (deterministic)

    float dT = Tf - ti;
    float contrib = 0.f;
#pragma unroll
    for (int d = 0; d < D; d++)
        contrib += alphas[d * D + ei] * (1.f - ex2(-b2s[d * D + ei] * dT));

    double v = (double)logf(s) - (double)contrib;

    __shared__ double red[TILE];
    red[tid] = v;
    __syncthreads();
#pragma unroll
    for (int off = TILE / 2; off > 0; off >>= 1) {
        if (tid < off) red[tid] += red[tid + off];
        __syncthreads();
    }
    if (tid == 0) g_block[it] = red[0];
}

// ---- kernel 3: final scalar ----
__global__ void k_out(const int* __restrict__ Tp, float* __restrict__ out) {
    if (threadIdx.x == 0) {
        float  Tf = decodeT(Tp);
        double s  = 0.0;
        for (int b = 0; b < NT; b++) s += g_block[b];
        double musum = 0.0;
        for (int d = 0; d < D; d++) musum += (double)g_mus[d];
        out[0] = (float)(s - musum * (double)Tf);
    }
}

extern "C" void kernel_launch(void* const* d_in, const int* in_sizes, int n_in,
                              void* d_out, int out_size) {
    const float* t  = (const float*)d_in[0];
    const int*   et = (const int*)d_in[1];
    const float* mu = (const float*)d_in[2];
    const float* la = (const float*)d_in[3];
    const float* lb = (const float*)d_in[4];
    const int*   Tp = (const int*)d_in[5];

    k_tables<<<1, 128>>>(mu, la, lb);
    k_tiles<<<NPAIRS, TILE>>>(t, et);
    k_final<<<NT, TILE>>>(t, et, Tp);
    k_out<<<1, 32>>>(Tp, (float*)d_out);
}

// round 2
// speedup vs baseline: 1.1761x; 1.1761x over previous
#include <cuda_runtime.h>
#include <math.h>

#define N 8192
#define D 10
#define TILE 256
#define NT (N / TILE)     // 32 tiles
#define PAD 11

// ---- persistent device scratch (no allocation) ----
__device__ float g_H[NT * D * D];
__device__ float g_P[NT * D * D];
__device__ long long          g_sum  = 0;   // fixed-point accumulator (2^-32)
__device__ unsigned long long g_ctr1 = 0;   // phase-1 arrival tickets (monotone)
__device__ unsigned long long g_ctr2 = 0;   // phase-3 finish tickets (monotone)
__device__ unsigned long long g_flag = 0;   // scan-done epoch flag (monotone)

__device__ __forceinline__ float ex2(float x) {
    float y;
    asm("ex2.approx.ftz.f32 %0, %1;" : "=f"(y) : "f"(x));
    return y;
}
__device__ __forceinline__ float softplus_f(float x) {
    return fmaxf(x, 0.f) + log1pf(expf(-fabsf(x)));
}
// T may arrive as int32(100) or float32(100.0)
__device__ __forceinline__ float decodeT(const int* Tp) {
    int b = *Tp;
    if (b >= 0 && b < (1 << 23)) return (float)b;
    return __int_as_float(b);
}

__global__ void __launch_bounds__(TILE)
hawkes_fused(const float* __restrict__ t, const int* __restrict__ et,
             const float* __restrict__ mu, const float* __restrict__ la,
             const float* __restrict__ lb, const int* __restrict__ Tp,
             float* __restrict__ out) {
    const int tid = threadIdx.x;
    const int it  = blockIdx.x;

    __shared__ float ts[TILE];
    __shared__ int   es[TILE];
    __shared__ float b2s[D * D], abt[D * D], alphas[D * D], mus[D];
    __shared__ float F[TILE * PAD], G[TILE * PAD];
    __shared__ float Hp[2][D * D];
    __shared__ float Psm[D * PAD];
    __shared__ double red[TILE];
    __shared__ unsigned long long tick_s;

    // ---- tables (redundant per block, ~100 softplus) + tile load ----
    if (tid < D * D) {
        float a = softplus_f(la[tid]);
        float b = softplus_f(lb[tid]);
        alphas[tid] = a;
        b2s[tid]    = b * 1.4426950408889634f;
        abt[tid]    = a * b;
    }
    if (tid >= 128 && tid < 128 + D) mus[tid - 128] = softplus_f(mu[tid - 128]);

    const int i  = it * TILE + tid;
    ts[tid] = t[i];
    es[tid] = et[i];
    __syncthreads();

    const float tref = ts[TILE - 1];
    const float ti   = ts[tid];
    const int   ei   = es[tid];
    const float dtj  = ti - tref;   // <= 0 within tile

    // G_j[k] = exp(-beta[k][e_j]*(tref - t_j)) <= 1
#pragma unroll
    for (int k = 0; k < D; k++)
        G[tid * PAD + k] = ex2(b2s[k * D + ei] * dtj);
    // F_i[m] = alpha*beta[e_i][m] * exp(+beta[e_i][m]*(tref - t_i))
#pragma unroll
    for (int m = 0; m < D; m++)
        F[tid * PAD + m] = abt[ei * D + m] * ex2(-b2s[ei * D + m] * dtj);
    __syncthreads();

    // ---- H partials: H[m][k] = sum_{j: e_j=m} G_j[k]  (two halves, fixed order) ----
    if (tid < 2 * D * D) {
        int half = tid / (D * D), e = tid % (D * D);
        int m = e / D, kk = e % D;
        float acc = 0.f;
        int j0 = half * (TILE / 2);
        for (int j = j0; j < j0 + TILE / 2; j++)
            if (es[j] == m) acc += G[j * PAD + kk];
        Hp[half][e] = acc;
    }

    // ---- in-tile strict-lower-triangle (diagonal block) ----
    float diag = 0.f;
    {
        const float* Frow = &F[tid * PAD];
        for (int j = 0; j < tid; j++) {
            int ej = es[j];
            diag = fmaf(Frow[ej], G[j * PAD + ei], diag);
        }
    }
    __syncthreads();

    if (tid < D * D) {
        g_H[it * D * D + tid] = Hp[0][tid] + Hp[1][tid];
        __threadfence();   // release H before ticket
    }
    __syncthreads();

    if (tid == 0) tick_s = atomicAdd(&g_ctr1, 1ULL);
    __syncthreads();
    const unsigned long long tick  = tick_s;
    const unsigned long long epoch = tick / NT;
    const bool last = (tick % NT) == (NT - 1);

    // ---- scan over tiles: P_s = H_s + P_{s-1}*exp(-beta[k][m]*(tref_s - tref_{s-1})) ----
    if (last) {
        __threadfence();   // acquire all H
        if (tid < D * D) {
            const int m = tid / D, kk = tid % D;
            const float b2 = b2s[kk * D + m];
            float P = 0.f, prev = 0.f;
            for (int s = 0; s < NT; s++) {
                float trs = t[s * TILE + TILE - 1];
                float dec = (s == 0) ? 0.f : ex2(-b2 * (trs - prev));
                P = g_H[s * D * D + tid] + P * dec;
                g_P[s * D * D + tid] = P;
                prev = trs;
            }
            __threadfence();   // release P
        }
        __syncthreads();
        if (tid == 0) atomicExch(&g_flag, epoch + 1);
    } else {
        if (tid == 0) {
            while (*(volatile unsigned long long*)&g_flag < epoch + 1)
                __nanosleep(64);
        }
    }
    __syncthreads();
    __threadfence();       // acquire P

    // ---- finalize per event ----
    if (it > 0 && tid < D * D)
        Psm[(tid / D) * PAD + (tid % D)] = g_P[(it - 1) * D * D + tid];
    __syncthreads();

    float cross = 0.f;
    if (it > 0) {
        const float trefp = t[it * TILE - 1];   // last time of previous tile
        const float dti   = ti - trefp;         // >= 0
#pragma unroll
        for (int m = 0; m < D; m++) {
            float Fb = abt[ei * D + m] * ex2(-b2s[ei * D + m] * dti);
            cross = fmaf(Fb, Psm[m * PAD + ei], cross);
        }
    }

    const float Tf   = decodeT(Tp);
    const float inten = mus[ei] + diag + cross;
    const float dT   = Tf - ti;
    float contrib = 0.f;
#pragma unroll
    for (int d = 0; d < D; d++)
        contrib += alphas[d * D + ei] * (1.f - ex2(-b2s[d * D + ei] * dT));

    red[tid] = (double)logf(inten) - (double)contrib;
    __syncthreads();
#pragma unroll
    for (int off = TILE / 2; off > 0; off >>= 1) {
        if (tid < off) red[tid] += red[tid + off];
        __syncthreads();
    }

    // ---- deterministic fixed-point global accumulation; last finisher writes out ----
    if (tid == 0) {
        long long q = __double2ll_rn(red[0] * 4294967296.0);
        atomicAdd((unsigned long long*)&g_sum, (unsigned long long)q);
        __threadfence();
        unsigned long long t2 = atomicAdd(&g_ctr2, 1ULL);
        if ((t2 % NT) == (NT - 1)) {
            __threadfence();
            long long tot = (long long)atomicExch((unsigned long long*)&g_sum, 0ULL);
            double s = (double)tot / 4294967296.0;
            double musum = 0.0;
#pragma unroll
            for (int d = 0; d < D; d++) musum += (double)mus[d];
            out[0] = (float)(s - musum * (double)Tf);
        }
    }
}

extern "C" void kernel_launch(void* const* d_in, const int* in_sizes, int n_in,
                              void* d_out, int out_size) {
    const float* t  = (const float*)d_in[0];
    const int*   et = (const int*)d_in[1];
    const float* mu = (const float*)d_in[2];
    const float* la = (const float*)d_in[3];
    const float* lb = (const float*)d_in[4];
    const int*   Tp = (const int*)d_in[5];

    hawkes_fused<<<NT, TILE>>>(t, et, mu, la, lb, Tp, (float*)d_out);
}

// round 3
// speedup vs baseline: 1.8153x; 1.5435x over previous
#include <cuda_runtime.h>
#include <math.h>

#define N 8192
#define D 10
#define DD (D * D)
#define TILE 256
#define NT (N / TILE)     // 32 tiles
#define PAD 11
#define NSB (TILE / 32)   // 8 sub-blocks per tile

// ---- persistent device scratch (no allocation) ----
__device__ float              g_H[NT * DD];
__device__ unsigned int       g_hflag[NT];  // monotone epoch flags
__device__ long long          g_sum  = 0;   // fixed-point accumulator (2^-32)
__device__ unsigned long long g_ctr1 = 0;   // arrival tickets (monotone)
__device__ unsigned long long g_ctr2 = 0;   // finish tickets (monotone)

__device__ __forceinline__ float ex2(float x) {
    float y;
    asm("ex2.approx.ftz.f32 %0, %1;" : "=f"(y) : "f"(x));
    return y;
}
__device__ __forceinline__ float softplus_f(float x) {
    return fmaxf(x, 0.f) + log1pf(expf(-fabsf(x)));
}
__device__ __forceinline__ float decodeT(const int* Tp) {
    int b = *Tp;
    if (b >= 0 && b < (1 << 23)) return (float)b;  // int32 T
    return __int_as_float(b);                      // float32 T
}

__global__ void __launch_bounds__(TILE)
hawkes_fused(const float* __restrict__ t, const int* __restrict__ et,
             const float* __restrict__ mu, const float* __restrict__ la,
             const float* __restrict__ lb, const int* __restrict__ Tp,
             float* __restrict__ out) {
    const int tid = threadIdx.x;
    const int it  = blockIdx.x;

    __shared__ float ts[TILE];
    __shared__ int   es[TILE];
    __shared__ float b2s[DD], abt[DD], alphas[DD], mus[D];
    __shared__ float F[TILE * PAD], G[TILE * PAD];
    __shared__ float subH[NSB][DD];     // per-sub-block H, then inclusive prefix
    __shared__ float Psm[D * PAD];      // cross-tile P anchored at own tref
    __shared__ float trefs[NT];         // last time of each tile
    __shared__ double red[NSB];
    __shared__ unsigned long long tick_s;

    // ---- tables (redundant per block) + tile load + tref gather ----
    if (tid < DD) {
        float a = softplus_f(la[tid]);
        float b = softplus_f(lb[tid]);
        alphas[tid] = a;
        b2s[tid]    = b * 1.4426950408889634f;
        abt[tid]    = a * b;
    }
    if (tid >= 128 && tid < 128 + D) mus[tid - 128] = softplus_f(mu[tid - 128]);
    if (tid >= 160 && tid < 160 + NT) trefs[tid - 160] = t[(tid - 160) * TILE + TILE - 1];

    const int i = it * TILE + tid;
    ts[tid] = t[i];
    es[tid] = et[i];
    __syncthreads();

    const float tref = trefs[it];
    const float ti   = ts[tid];
    const int   ei   = es[tid];
    const float dtj  = ti - tref;   // <= 0

    // G_j[k] = 2^(b2[k][e_j]*(t_j - tref)) <= 1 ; F_i[m] = ab[e_i][m]*2^(b2[e_i][m]*(tref - t_i))
#pragma unroll
    for (int k = 0; k < D; k++)
        G[tid * PAD + k] = ex2(b2s[k * D + ei] * dtj);
#pragma unroll
    for (int m = 0; m < D; m++)
        F[tid * PAD + m] = abt[ei * D + m] * ex2(-b2s[ei * D + m] * dtj);
    __syncthreads();

    // ---- per-sub-block H: subH[sb][m][k] = sum_{j in sb, e_j=m} G_j[k] ----
    for (int e = tid; e < NSB * DD; e += TILE) {
        int sb = e / DD, r = e % DD, m = r / D, kk = r % D;
        float acc = 0.f;
        int j0 = sb * 32;
#pragma unroll
        for (int j = 0; j < 32; j++) {
            bool hit = (es[j0 + j] == m);
            acc += hit ? G[(j0 + j) * PAD + kk] : 0.f;
        }
        subH[sb][r] = acc;
    }

    // ---- in-warp strict triangle (31 its, fully unrolled, predicated) ----
    float tri = 0.f;
    {
        const int base = tid & ~31;
        const int lid  = tid & 31;
#pragma unroll
        for (int jj = 0; jj < 31; jj++) {
            if (jj < lid) {
                int j  = base + jj;
                int ej = es[j];
                tri = fmaf(F[tid * PAD + ej], G[j * PAD + ei], tri);
            }
        }
    }
    __syncthreads();

    // inclusive prefix over sub-blocks (thread r owns column r)
    if (tid < DD) {
        float run = subH[0][tid];
#pragma unroll
        for (int sb = 1; sb < NSB; sb++) { run += subH[sb][tid]; subH[sb][tid] = run; }
        // publish full-tile H
        g_H[it * DD + tid] = run;
    }
    __threadfence();
    __syncthreads();

    // ---- cross-sub-block (within tile): exclusive prefix at sb-1 ----
    float crossSub = 0.f;
    {
        const int sb = tid >> 5;
        if (sb > 0) {
#pragma unroll
            for (int m = 0; m < D; m++)
                crossSub = fmaf(F[tid * PAD + m], subH[sb - 1][m * D + ei], crossSub);
        }
    }

    // ---- publish flag + spin on predecessors ----
    if (tid == 0) tick_s = atomicAdd(&g_ctr1, 1ULL);
    __syncthreads();
    const unsigned int epoch1 = (unsigned int)(tick_s / NT) + 1u;
    if (tid == 0) atomicExch(&g_hflag[it], epoch1);
    if (tid < it) {
        while (*(volatile unsigned int*)&g_hflag[tid] < epoch1)
            __nanosleep(32);
    }
    __syncthreads();
    __threadfence();

    // ---- cross-tile P (direct sum, anchored at own tref) ----
    if (tid < DD) {
        const int m = tid / D, kk = tid % D;
        const float b2 = b2s[kk * D + m];
        float acc = 0.f;
        for (int s = 0; s < it; s++) {
            float Hs  = __ldcg(&g_H[s * DD + tid]);
            float dec = ex2(-b2 * (tref - trefs[s]));
            acc = fmaf(Hs, dec, acc);
        }
        Psm[m * PAD + kk] = acc;
    }
    __syncthreads();

    float crossTile = 0.f;
    if (it > 0) {
#pragma unroll
        for (int m = 0; m < D; m++)
            crossTile = fmaf(F[tid * PAD + m], Psm[m * PAD + ei], crossTile);
    }

    // ---- finalize per event ----
    const float Tf    = decodeT(Tp);
    const float inten = mus[ei] + tri + crossSub + crossTile;
    const float dT    = Tf - ti;
    float contrib = 0.f;
#pragma unroll
    for (int d = 0; d < D; d++)
        contrib += alphas[d * D + ei] * (1.f - ex2(-b2s[d * D + ei] * dT));

    double v = (double)logf(inten) - (double)contrib;

    // ---- warp-shuffle double reduction ----
#pragma unroll
    for (int off = 16; off > 0; off >>= 1)
        v += __shfl_down_sync(0xffffffffu, v, off);
    if ((tid & 31) == 0) red[tid >> 5] = v;
    __syncthreads();

    if (tid == 0) {
        double bs = 0.0;
#pragma unroll
        for (int w = 0; w < NSB; w++) bs += red[w];
        long long q = __double2ll_rn(bs * 4294967296.0);
        atomicAdd((unsigned long long*)&g_sum, (unsigned long long)q);
        __threadfence();
        unsigned long long t2 = atomicAdd(&g_ctr2, 1ULL);
        if ((t2 % NT) == (NT - 1)) {
            __threadfence();
            long long tot = (long long)atomicExch((unsigned long long*)&g_sum, 0ULL);
            double s = (double)tot / 4294967296.0;
            double musum = 0.0;
#pragma unroll
            for (int d = 0; d < D; d++) musum += (double)mus[d];
            out[0] = (float)(s - musum * (double)Tf);
        }
    }
}

extern "C" void kernel_launch(void* const* d_in, const int* in_sizes, int n_in,
                              void* d_out, int out_size) {
    const float* t  = (const float*)d_in[0];
    const int*   et = (const int*)d_in[1];
    const float* mu = (const float*)d_in[2];
    const float* la = (const float*)d_in[3];
    const float* lb = (const float*)d_in[4];
    const int*   Tp = (const int*)d_in[5];

    hawkes_fused<<<NT, TILE>>>(t, et, mu, la, lb, Tp, (float*)d_out);
}